// round 3
// baseline (speedup 1.0000x reference)
#include <cuda_runtime.h>
#include <cstddef>

constexpr int B = 4, C = 16, H = 512, W = 960;
constexpr int HW   = H * W;            // 491,520
constexpr int NPIX = B * HW;
constexpr int THREADS = 256;
constexpr int BLOCKS_PER_BATCH = HW / THREADS;  // 1920

// Accumulation scratch, zero-initialized at module load.
// norm re-zeros after reading, so every kernel_launch call sees zeros.
__device__ __align__(16) float g_vals[(size_t)NPIX * 16];  // [pix][16ch], 64B rows
__device__ float g_met[(size_t)NPIX];                      // splatted exp(metric)

__device__ __forceinline__ void red_add_v4(float* p, float a, float b, float c, float d) {
    asm volatile("red.global.add.v4.f32 [%0], {%1, %2, %3, %4};"
                 :: "l"(p), "f"(a), "f"(b), "f"(c), "f"(d) : "memory");
}
__device__ __forceinline__ void red_add_f32(float* p, float a) {
    asm volatile("red.global.add.f32 [%0], %1;" :: "l"(p), "f"(a) : "memory");
}

__device__ __forceinline__ void splat_pixel(
    int b, int p,
    const float* __restrict__ in,
    const float* __restrict__ flow,
    const float* __restrict__ metric)
{
    const int idx = b * HW + p;
    const int y = p / W;
    const int x = p - y * W;

    const float fx = (float)x + flow[(size_t)b * 2 * HW + p];
    const float fy = (float)y + flow[(size_t)b * 2 * HW + HW + p];
    const float m  = __expf(metric[idx]);

    const float x0f = floorf(fx), y0f = floorf(fy);
    const int   x0  = (int)x0f,   y0  = (int)y0f;
    const float wx1 = fx - x0f, wy1 = fy - y0f;
    const float wx0 = 1.0f - wx1, wy0 = 1.0f - wy1;

    float v[16];
    const float* inp = in + (size_t)b * C * HW + p;
#pragma unroll
    for (int c = 0; c < 16; ++c) v[c] = inp[(size_t)c * HW] * m;

#pragma unroll
    for (int cy = 0; cy < 2; ++cy) {
        const int yi = y0 + cy;
        if (yi < 0 || yi >= H) continue;
        const float wy = cy ? wy1 : wy0;
#pragma unroll
        for (int cx = 0; cx < 2; ++cx) {
            const int xi = x0 + cx;
            if (xi < 0 || xi >= W) continue;
            const float w = wy * (cx ? wx1 : wx0);
            const size_t d = (size_t)b * HW + (size_t)yi * W + xi;
            float* dst = g_vals + d * 16;
#pragma unroll
            for (int q = 0; q < 4; ++q) {
                red_add_v4(dst + q * 4,
                           v[q * 4 + 0] * w, v[q * 4 + 1] * w,
                           v[q * 4 + 2] * w, v[q * 4 + 3] * w);
            }
            red_add_f32(g_met + d, m * w);
        }
    }
}

__device__ __forceinline__ void norm_pixel(int b, int p, float* __restrict__ out) {
    const int idx = b * HW + p;
    float4* s = reinterpret_cast<float4*>(g_vals + (size_t)idx * 16);
    // Evict-first loads: this data is dead after the read.
    float4 a0 = __ldcs(s + 0);
    float4 a1 = __ldcs(s + 1);
    float4 a2 = __ldcs(s + 2);
    float4 a3 = __ldcs(s + 3);
    float  nrm = __ldcs(g_met + idx) + 1e-7f;
    float  inv = 1.0f / nrm;

    float* o = out + (size_t)b * C * HW + p;
    __stcs(o + (size_t)0  * HW, a0.x * inv);
    __stcs(o + (size_t)1  * HW, a0.y * inv);
    __stcs(o + (size_t)2  * HW, a0.z * inv);
    __stcs(o + (size_t)3  * HW, a0.w * inv);
    __stcs(o + (size_t)4  * HW, a1.x * inv);
    __stcs(o + (size_t)5  * HW, a1.y * inv);
    __stcs(o + (size_t)6  * HW, a1.z * inv);
    __stcs(o + (size_t)7  * HW, a1.w * inv);
    __stcs(o + (size_t)8  * HW, a2.x * inv);
    __stcs(o + (size_t)9  * HW, a2.y * inv);
    __stcs(o + (size_t)10 * HW, a2.z * inv);
    __stcs(o + (size_t)11 * HW, a2.w * inv);
    __stcs(o + (size_t)12 * HW, a3.x * inv);
    __stcs(o + (size_t)13 * HW, a3.y * inv);
    __stcs(o + (size_t)14 * HW, a3.z * inv);
    __stcs(o + (size_t)15 * HW, a3.w * inv);

    // Restore zeros for the next call (evict-first: not needed until next call).
    const float4 z = make_float4(0.f, 0.f, 0.f, 0.f);
    __stcs(s + 0, z); __stcs(s + 1, z); __stcs(s + 2, z); __stcs(s + 3, z);
    __stcs(g_met + idx, 0.0f);
}

// Fused stage kernel: even blocks splat batch `sb`, odd blocks normalize batch `nb`.
// When only one role is active, all blocks take that role.
__global__ void __launch_bounds__(THREADS)
stage_kernel(const float* __restrict__ in,
             const float* __restrict__ flow,
             const float* __restrict__ metric,
             float* __restrict__ out,
             int sb, int nb)
{
    int role, rb;
    if (sb >= 0 && nb >= 0) { role = blockIdx.x & 1; rb = blockIdx.x >> 1; }
    else if (sb >= 0)       { role = 0;              rb = blockIdx.x; }
    else                    { role = 1;              rb = blockIdx.x; }

    const int p = rb * THREADS + threadIdx.x;
    if (role == 0) splat_pixel(sb, p, in, flow, metric);
    else           norm_pixel(nb, p, out);
}

extern "C" void kernel_launch(void* const* d_in, const int* in_sizes, int n_in,
                              void* d_out, int out_size) {
    const float* ten_in     = (const float*)d_in[0];
    const float* ten_flow   = (const float*)d_in[1];
    const float* ten_metric = (const float*)d_in[2];
    float* out = (float*)d_out;

    for (int i = 0; i <= B; ++i) {
        const int sb = (i < B) ? i : -1;
        const int nb = i - 1;                       // -1 on first stage
        const int nroles = (sb >= 0) + (nb >= 0);
        stage_kernel<<<nroles * BLOCKS_PER_BATCH, THREADS>>>(
            ten_in, ten_flow, ten_metric, out, sb, nb);
    }
}

// round 4
// speedup vs baseline: 1.7008x; 1.7008x over previous
#include <cuda_runtime.h>
#include <cuda_fp16.h>
#include <cstdint>
#include <cstddef>

constexpr int B = 4, C = 16, H = 512, W = 960;
constexpr int HW   = H * W;
constexpr int NPIX = B * HW;           // 1,966,080

// Accumulation scratch, zero-initialized at module load.
// norm_kernel re-zeros after reading, so every call sees zeros.
// Channels accumulate in fp16 (8 x half2 = 32B per pixel); metric in fp32.
__device__ __align__(32) __half2 g_vals[(size_t)NPIX * 8];
__device__ float g_met[(size_t)NPIX];

__device__ __forceinline__ void red_add_v4h2(__half2* p, uint32_t a, uint32_t b,
                                             uint32_t c, uint32_t d) {
    asm volatile("red.global.add.noftz.v4.f16x2 [%0], {%1, %2, %3, %4};"
                 :: "l"(p), "r"(a), "r"(b), "r"(c), "r"(d) : "memory");
}
__device__ __forceinline__ void red_add_f32(float* p, float a) {
    asm volatile("red.global.add.f32 [%0], %1;" :: "l"(p), "f"(a) : "memory");
}
__device__ __forceinline__ uint32_t pack2(float lo, float hi) {
    __half2 h = __floats2half2_rn(lo, hi);
    return *reinterpret_cast<uint32_t*>(&h);
}

__global__ void __launch_bounds__(256)
splat_kernel(const float* __restrict__ in,
             const float* __restrict__ flow,
             const float* __restrict__ metric) {
    int idx = blockIdx.x * blockDim.x + threadIdx.x;
    if (idx >= NPIX) return;
    int b = idx / HW;
    int p = idx - b * HW;
    int y = p / W;
    int x = p - y * W;

    const float fx = (float)x + flow[(size_t)b * 2 * HW + p];
    const float fy = (float)y + flow[(size_t)b * 2 * HW + HW + p];
    const float m  = __expf(metric[idx]);

    const float x0f = floorf(fx), y0f = floorf(fy);
    const int   x0  = (int)x0f,   y0  = (int)y0f;
    const float wx1 = fx - x0f, wy1 = fy - y0f;
    const float wx0 = 1.0f - wx1, wy0 = 1.0f - wy1;

    // Pre-scale channel values by exp(metric) (fp32)
    float v[16];
    const float* inp = in + (size_t)b * C * HW + p;
#pragma unroll
    for (int c = 0; c < 16; ++c) v[c] = inp[(size_t)c * HW] * m;

#pragma unroll
    for (int cy = 0; cy < 2; ++cy) {
        const int yi = y0 + cy;
        if (yi < 0 || yi >= H) continue;
        const float wy = cy ? wy1 : wy0;
#pragma unroll
        for (int cx = 0; cx < 2; ++cx) {
            const int xi = x0 + cx;
            if (xi < 0 || xi >= W) continue;
            const float w = wy * (cx ? wx1 : wx0);
            const size_t d = (size_t)b * HW + (size_t)yi * W + xi;
            __half2* dst = g_vals + d * 8;
            // Products in fp32, single rn-rounding into fp16 addends.
            uint32_t r0 = pack2(v[0]  * w, v[1]  * w);
            uint32_t r1 = pack2(v[2]  * w, v[3]  * w);
            uint32_t r2 = pack2(v[4]  * w, v[5]  * w);
            uint32_t r3 = pack2(v[6]  * w, v[7]  * w);
            uint32_t r4 = pack2(v[8]  * w, v[9]  * w);
            uint32_t r5 = pack2(v[10] * w, v[11] * w);
            uint32_t r6 = pack2(v[12] * w, v[13] * w);
            uint32_t r7 = pack2(v[14] * w, v[15] * w);
            red_add_v4h2(dst + 0, r0, r1, r2, r3);
            red_add_v4h2(dst + 4, r4, r5, r6, r7);
            red_add_f32(g_met + d, m * w);
        }
    }
}

__global__ void __launch_bounds__(256)
norm_kernel(float* __restrict__ out) {
    int idx = blockIdx.x * blockDim.x + threadIdx.x;
    if (idx >= NPIX) return;
    int b = idx / HW;
    int p = idx - b * HW;

    uint4* s = reinterpret_cast<uint4*>(g_vals + (size_t)idx * 8);
    uint4 u0 = __ldcs(s + 0);
    uint4 u1 = __ldcs(s + 1);
    float nrm = __ldcs(g_met + idx) + 1e-7f;
    float inv = 1.0f / nrm;

    float* o = out + (size_t)b * C * HW + p;
    const uint32_t uw[8] = {u0.x, u0.y, u0.z, u0.w, u1.x, u1.y, u1.z, u1.w};
#pragma unroll
    for (int q = 0; q < 8; ++q) {
        __half2 h = *reinterpret_cast<const __half2*>(&uw[q]);
        float2  f = __half22float2(h);
        __stcs(o + (size_t)(2 * q)     * HW, f.x * inv);
        __stcs(o + (size_t)(2 * q + 1) * HW, f.y * inv);
    }

    // Restore zeros for the next call (replaces a standalone memset pass).
    const uint4 z = make_uint4(0u, 0u, 0u, 0u);
    __stcs(s + 0, z);
    __stcs(s + 1, z);
    __stcs(g_met + idx, 0.0f);
}

extern "C" void kernel_launch(void* const* d_in, const int* in_sizes, int n_in,
                              void* d_out, int out_size) {
    const float* ten_in     = (const float*)d_in[0];
    const float* ten_flow   = (const float*)d_in[1];
    const float* ten_metric = (const float*)d_in[2];
    float* out = (float*)d_out;

    const int threads = 256;
    const int blocks  = (NPIX + threads - 1) / threads;
    splat_kernel<<<blocks, threads>>>(ten_in, ten_flow, ten_metric);
    norm_kernel<<<blocks, threads>>>(out);
}